// round 11
// baseline (speedup 1.0000x reference)
#include <cuda_runtime.h>
#include <math.h>
#include <stdint.h>

#define NNODES 50000
#define NEDGES 800000
#define ETOT   (NEDGES + NNODES)
#define DIN    256
#define HID    128

// ---------------- scratch (static device globals; no allocation) -------------
__device__ float g_XLR[NNODES * 256];    // layer-0 [xl | xr] (51.2 MB)
__device__ float g_XLR2[NNODES * 256];   // layer-1 [xl | xr] (51.2 MB)
__device__ float g_H[NNODES * HID];      // layer output (25.6 MB)
__device__ int   g_deg[NNODES];
__device__ int   g_off[NNODES + 1];
__device__ int   g_cur[NNODES];
__device__ int   g_csr[ETOT];

// ---------------- CSR build --------------------------------------------------
__global__ void k_deg_count(const int* __restrict__ ei) {
    int e = blockIdx.x * blockDim.x + threadIdx.x;
    if (e < NEDGES) atomicAdd(&g_deg[ei[NEDGES + e]], 1);
}

__global__ void k_scan() {
    __shared__ int sh[1024];
    const int n = NNODES;
    int tid = threadIdx.x;
    const int chunk = (n + 1023) / 1024;
    int start = tid * chunk;
    int s = 0;
    for (int i = 0; i < chunk; i++) {
        int idx = start + i;
        if (idx < n) s += g_deg[idx] + 1;
    }
    sh[tid] = s;
    __syncthreads();
    for (int o = 1; o < 1024; o <<= 1) {
        int v = (tid >= o) ? sh[tid - o] : 0;
        __syncthreads();
        sh[tid] += v;
        __syncthreads();
    }
    int run = tid ? sh[tid - 1] : 0;
    for (int i = 0; i < chunk; i++) {
        int idx = start + i;
        if (idx < n) {
            g_off[idx] = run;
            g_cur[idx] = run;
            run += g_deg[idx] + 1;
        }
    }
    if (tid == 1023) g_off[n] = sh[1023];
}

__global__ void k_fill(const int* __restrict__ ei) {
    int e = blockIdx.x * blockDim.x + threadIdx.x;
    if (e >= ETOT) return;
    int src, dst;
    if (e < NEDGES) { src = ei[e]; dst = ei[NEDGES + e]; }
    else            { src = dst = e - NEDGES; }
    int pos = atomicAdd(&g_cur[dst], 1);
    g_csr[pos] = src;
}

// ---------------- TF32 tensor-core GEMM, 4-stage cp.async pipeline -----------
// Out rows [mbase + blockIdx.x*128 ...). Identical body to the 342us version.
#define ST    4
#define PAD   20
#define STGW  (128 * PAD)
#define GSMEM (ST * 2 * STGW * 4)

__device__ __forceinline__ unsigned f2tf32(float f) {
    unsigned u;
    asm("cvt.rna.tf32.f32 %0, %1;" : "=r"(u) : "f"(f));
    return u;
}
__device__ __forceinline__ void cp16(uint32_t sa, const void* g) {
    asm volatile("cp.async.cg.shared.global [%0], [%1], 16;" :: "r"(sa), "l"(g));
}

__global__ void __launch_bounds__(256, 2)
k_gemm_tf32(const float* __restrict__ X,
            const float* __restrict__ Wl,
            const float* __restrict__ Wr,
            float* __restrict__ Out, int K, int mbase) {
    extern __shared__ float sm[];
    float* Asm = sm;
    float* Bsm = sm + ST * STGW;
    uint32_t Abase = (uint32_t)__cvta_generic_to_shared(Asm);
    uint32_t Bbase = (uint32_t)__cvta_generic_to_shared(Bsm);

    int t = threadIdx.x;
    int m0 = mbase + blockIdx.x * 128, n0 = blockIdx.y * 128;
    int lane = t & 31;
    int wid = t >> 5;
    int wm = (wid >> 2) * 64;
    int wn = (wid & 3) * 32;
    int g = lane >> 2, c = lane & 3;

    int rowA0 = t >> 2, rowA1 = (t + 256) >> 2;
    int q0 = (t & 3) * 4;
    int ga0 = m0 + rowA0; if (ga0 >= NNODES) ga0 = 0;
    int ga1 = m0 + rowA1; if (ga1 >= NNODES) ga1 = 0;
    const float* ap0 = X + (size_t)ga0 * K + q0;
    const float* ap1 = X + (size_t)ga1 * K + q0;
    const float* Wsel = (n0 == 0) ? Wl : Wr;
    const float* bp0 = Wsel + (size_t)rowA0 * K + q0;
    const float* bp1 = Wsel + (size_t)rowA1 * K + q0;
    uint32_t sa0 = Abase + (uint32_t)(rowA0 * PAD + q0) * 4;
    uint32_t sa1 = Abase + (uint32_t)(rowA1 * PAD + q0) * 4;
    uint32_t sb0 = Bbase + (uint32_t)(rowA0 * PAD + q0) * 4;
    uint32_t sb1 = Bbase + (uint32_t)(rowA1 * PAD + q0) * 4;

    int nk = K >> 4;

#define ISSUE(slot, kt_)                                             \
    {   uint32_t so = (uint32_t)(slot) * (STGW * 4);                 \
        size_t go = (size_t)(kt_) * 16;                              \
        cp16(sa0 + so, ap0 + go); cp16(sa1 + so, ap1 + go);          \
        cp16(sb0 + so, bp0 + go); cp16(sb1 + so, bp1 + go); }

#pragma unroll
    for (int s = 0; s < ST - 1; s++) {
        if (s < nk) ISSUE(s, s);
        asm volatile("cp.async.commit_group;");
    }

    float acc[4][4][4];
#pragma unroll
    for (int i = 0; i < 4; i++)
#pragma unroll
        for (int j = 0; j < 4; j++)
#pragma unroll
            for (int q = 0; q < 4; q++) acc[i][j][q] = 0.f;

    for (int kt = 0; kt < nk; kt++) {
        asm volatile("cp.async.wait_group %0;" :: "n"(ST - 2));
        __syncthreads();

        int nxt = kt + ST - 1;
        if (nxt < nk) ISSUE(nxt % ST, nxt);
        asm volatile("cp.async.commit_group;");

        const float* As = Asm + (kt % ST) * STGW;
        const float* Bs = Bsm + (kt % ST) * STGW;
#pragma unroll
        for (int s = 0; s < 2; s++) {
            int ks = s * 8;
            unsigned bf[4][2];
#pragma unroll
            for (int j = 0; j < 4; j++) {
                const float* br = Bs + (wn + j * 8 + g) * PAD + ks + c;
                bf[j][0] = f2tf32(br[0]);
                bf[j][1] = f2tf32(br[4]);
            }
#pragma unroll
            for (int i = 0; i < 4; i++) {
                const float* ar0 = As + (wm + i * 16 + g) * PAD + ks + c;
                const float* ar1 = As + (wm + i * 16 + g + 8) * PAD + ks + c;
                unsigned a0 = f2tf32(ar0[0]);
                unsigned a1 = f2tf32(ar1[0]);
                unsigned a2 = f2tf32(ar0[4]);
                unsigned a3 = f2tf32(ar1[4]);
#pragma unroll
                for (int j = 0; j < 4; j++) {
                    asm volatile(
                        "mma.sync.aligned.m16n8k8.row.col.f32.tf32.tf32.f32 "
                        "{%0,%1,%2,%3}, {%4,%5,%6,%7}, {%8,%9}, {%0,%1,%2,%3};"
                        : "+f"(acc[i][j][0]), "+f"(acc[i][j][1]),
                          "+f"(acc[i][j][2]), "+f"(acc[i][j][3])
                        : "r"(a0), "r"(a1), "r"(a2), "r"(a3),
                          "r"(bf[j][0]), "r"(bf[j][1]));
                }
            }
        }
    }
#undef ISSUE

#pragma unroll
    for (int i = 0; i < 4; i++) {
        int row0 = m0 + wm + i * 16 + g;
        int row1 = row0 + 8;
#pragma unroll
        for (int j = 0; j < 4; j++) {
            int col = n0 + wn + j * 8 + c * 2;
            if (row0 < NNODES)
                *(float2*)(Out + (size_t)row0 * 256 + col) =
                    make_float2(acc[i][j][0], acc[i][j][1]);
            if (row1 < NNODES)
                *(float2*)(Out + (size_t)row1 * 256 + col) =
                    make_float2(acc[i][j][2], acc[i][j][3]);
        }
    }
}

// ---------------- GATv2 attention: warp-per-dst, batch-4 (R6 body) -----------
__global__ void k_attn(const float* __restrict__ XLR,
                       const float* __restrict__ att,
                       const float* __restrict__ bias,
                       float* __restrict__ H, int lo, int hi) {
    int warp = lo + ((blockIdx.x * blockDim.x + threadIdx.x) >> 5);
    int lane = threadIdx.x & 31;
    if (warp >= hi) return;
    int dst = warp;
    int c4 = lane << 2;

    float4 xr = *(const float4*)(XLR + (size_t)dst * 256 + 128 + c4);
    float4 av = *(const float4*)(att + c4);

    int beg = g_off[dst], end = g_off[dst + 1];

    float s = 0.f;
    float cx = 0.f, cy = 0.f, cz = 0.f, cw = 0.f;

#define EDGE(v)                                                             \
    {   float t0 = (v).x + xr.x, t1 = (v).y + xr.y;                         \
        float t2 = (v).z + xr.z, t3 = (v).w + xr.w;                         \
        t0 = (t0 > 0.f) ? t0 : 0.2f * t0;                                   \
        t1 = (t1 > 0.f) ? t1 : 0.2f * t1;                                   \
        t2 = (t2 > 0.f) ? t2 : 0.2f * t2;                                   \
        t3 = (t3 > 0.f) ? t3 : 0.2f * t3;                                   \
        float p = av.x * t0 + av.y * t1 + av.z * t2 + av.w * t3;            \
        p += __shfl_xor_sync(0xffffffffu, p, 1);                            \
        p += __shfl_xor_sync(0xffffffffu, p, 2);                            \
        p += __shfl_xor_sync(0xffffffffu, p, 4);                            \
        float w = __expf(p);                                                \
        s += w; cx += w * (v).x; cy += w * (v).y;                           \
        cz += w * (v).z; cw += w * (v).w; }

    int jj = beg;
    for (; jj + 4 <= end; jj += 4) {
        int s0 = g_csr[jj], s1 = g_csr[jj + 1];
        int s2 = g_csr[jj + 2], s3 = g_csr[jj + 3];
        float4 v0 = *(const float4*)(XLR + (size_t)s0 * 256 + c4);
        float4 v1 = *(const float4*)(XLR + (size_t)s1 * 256 + c4);
        float4 v2 = *(const float4*)(XLR + (size_t)s2 * 256 + c4);
        float4 v3 = *(const float4*)(XLR + (size_t)s3 * 256 + c4);
        EDGE(v0); EDGE(v1); EDGE(v2); EDGE(v3);
    }
    for (; jj < end; jj++) {
        int sn = g_csr[jj];
        float4 v = *(const float4*)(XLR + (size_t)sn * 256 + c4);
        EDGE(v);
    }
#undef EDGE

    float inv = 1.f / s;
    float4 bv = *(const float4*)(bias + c4);
    float4 o = make_float4(cx * inv + bv.x, cy * inv + bv.y,
                           cz * inv + bv.z, cw * inv + bv.w);
    *(float4*)(H + (size_t)dst * 128 + c4) = o;
}

// ---------------- down projection (rows [lo,hi)) -----------------------------
__global__ void k_down(const float* __restrict__ Hin,
                       const float* __restrict__ W,
                       const float* __restrict__ b,
                       float* __restrict__ Out, int lo) {
    __shared__ float Ws[128 * 33];
    __shared__ float Hs[8 * 128];
    int tid = threadIdx.x;
    for (int l = tid; l < 32 * 128; l += 256) {
        int c = l / 128, k = l % 128;
        Ws[k * 33 + c] = W[l];
    }
    int n0 = lo + blockIdx.x * 8;
    for (int l = tid; l < 8 * 128; l += 256)
        Hs[l] = Hin[(size_t)n0 * 128 + l];
    __syncthreads();
    int nd = tid >> 5, c = tid & 31;
    float acc = 0.f;
#pragma unroll 16
    for (int k = 0; k < 128; k++)
        acc += Hs[nd * 128 + k] * Ws[k * 33 + c];
    Out[(size_t)(n0 + nd) * 32 + c] = acc + b[c];
}

// ---------------- launch -----------------------------------------------------
#define NCHUNK 4
static const int CHB[NCHUNK + 1] = {0, 12544, 25088, 37632, 50000};

extern "C" void kernel_launch(void* const* d_in, const int* in_sizes, int n_in,
                              void* d_out, int out_size) {
    const float* x    = (const float*)d_in[0];
    const int*   ei   = (const int*)d_in[1];
    const float* Wl0  = (const float*)d_in[2];
    const float* Wr0  = (const float*)d_in[3];
    const float* att0 = (const float*)d_in[4];
    const float* b0   = (const float*)d_in[5];
    const float* Wl1  = (const float*)d_in[6];
    const float* Wr1  = (const float*)d_in[7];
    const float* att1 = (const float*)d_in[8];
    const float* b1   = (const float*)d_in[9];
    const float* dW   = (const float*)d_in[10];
    const float* db   = (const float*)d_in[11];
    float* out = (float*)d_out;

    float *xlr_p = nullptr, *xlr2_p = nullptr, *h_p = nullptr;
    int  *deg_p = nullptr;
    cudaGetSymbolAddress((void**)&xlr_p, g_XLR);
    cudaGetSymbolAddress((void**)&xlr2_p, g_XLR2);
    cudaGetSymbolAddress((void**)&h_p, g_H);
    cudaGetSymbolAddress((void**)&deg_p, g_deg);

    static cudaStream_t s2 = nullptr;
    static cudaEvent_t evFork = nullptr, evCSR = nullptr, evG1 = nullptr, evEnd = nullptr;
    static cudaEvent_t eA[NCHUNK] = {}, eB[NCHUNK] = {};
    if (!s2) {
        cudaFuncSetAttribute(k_gemm_tf32,
                             cudaFuncAttributeMaxDynamicSharedMemorySize, GSMEM);
        cudaStreamCreateWithFlags(&s2, cudaStreamNonBlocking);
        cudaEventCreateWithFlags(&evFork, cudaEventDisableTiming);
        cudaEventCreateWithFlags(&evCSR, cudaEventDisableTiming);
        cudaEventCreateWithFlags(&evG1, cudaEventDisableTiming);
        cudaEventCreateWithFlags(&evEnd, cudaEventDisableTiming);
        for (int i = 0; i < NCHUNK; i++) {
            cudaEventCreateWithFlags(&eA[i], cudaEventDisableTiming);
            cudaEventCreateWithFlags(&eB[i], cudaEventDisableTiming);
        }
    }

    cudaStream_t s0 = 0;

    // ---- fork: CSR build on s2 || GEMM layer 0 on s0 ----
    cudaEventRecord(evFork, s0);
    cudaStreamWaitEvent(s2, evFork, 0);

    cudaMemsetAsync(deg_p, 0, NNODES * sizeof(int), s2);
    k_deg_count<<<(NEDGES + 255) / 256, 256, 0, s2>>>(ei);
    k_scan<<<1, 1024, 0, s2>>>();
    k_fill<<<(ETOT + 255) / 256, 256, 0, s2>>>(ei);
    cudaEventRecord(evCSR, s2);

    dim3 gg((NNODES + 127) / 128, 2);
    k_gemm_tf32<<<gg, 256, GSMEM, s0>>>(x, Wl0, Wr0, xlr_p, DIN, 0);

    cudaStreamWaitEvent(s0, evCSR, 0);

    // ---- layer-0 attention chunks on s0; gemm1 chunks trail on s2 ----
    for (int i = 0; i < NCHUNK; i++) {
        int lo = CHB[i], hi = CHB[i + 1];
        int nb = ((hi - lo) * 32 + 255) / 256;
        k_attn<<<nb, 256, 0, s0>>>(xlr_p, att0, b0, h_p, lo, hi);
        cudaEventRecord(eA[i], s0);
    }
    for (int i = 0; i < NCHUNK; i++) {
        int lo = CHB[i], hi = CHB[i + 1];
        cudaStreamWaitEvent(s2, eA[i], 0);
        dim3 gc((hi - lo + 127) / 128, 2);
        k_gemm_tf32<<<gc, 256, GSMEM, s2>>>(h_p, Wl1, Wr1, xlr2_p, HID, lo);
    }
    cudaEventRecord(evG1, s2);
    cudaStreamWaitEvent(s0, evG1, 0);

    // ---- layer-1 attention chunks on s0; down-proj chunks trail on s2 ----
    for (int i = 0; i < NCHUNK; i++) {
        int lo = CHB[i], hi = CHB[i + 1];
        int nb = ((hi - lo) * 32 + 255) / 256;
        k_attn<<<nb, 256, 0, s0>>>(xlr2_p, att1, b1, h_p, lo, hi);
        cudaEventRecord(eB[i], s0);
    }
    for (int i = 0; i < NCHUNK; i++) {
        int lo = CHB[i], hi = CHB[i + 1];
        cudaStreamWaitEvent(s2, eB[i], 0);
        k_down<<<(hi - lo) / 8, 256, 0, s2>>>(h_p, dW, db, out, lo);
    }
    cudaEventRecord(evEnd, s2);
    cudaStreamWaitEvent(s0, evEnd, 0);
}

// round 12
// speedup vs baseline: 1.2845x; 1.2845x over previous
#include <cuda_runtime.h>
#include <math.h>
#include <stdint.h>

#define NNODES 50000
#define NEDGES 800000
#define ETOT   (NEDGES + NNODES)
#define DIN    256
#define HID    128

// ---------------- scratch (static device globals; no allocation) -------------
__device__ float g_XLR[NNODES * 256];   // fused [xl | xr] per node (51.2 MB)
__device__ float g_H[NNODES * HID];     // layer output (25.6 MB)
__device__ float g_W0[256 * DIN];       // pre-rounded [Wl0;Wr0] (tf32 values)
__device__ float g_W1[256 * HID];       // pre-rounded [Wl1;Wr1]
__device__ int   g_deg[NNODES];
__device__ int   g_off[NNODES + 1];
__device__ int   g_cur[NNODES];
__device__ int   g_csr[ETOT];

__device__ __forceinline__ unsigned f2tf32(float f) {
    unsigned u;
    asm("cvt.rna.tf32.f32 %0, %1;" : "=r"(u) : "f"(f));
    return u;
}
__device__ __forceinline__ float rnd_tf32(float f) {
    return __uint_as_float(f2tf32(f));
}

// ---------------- CSR build --------------------------------------------------
__global__ void k_deg_count(const int* __restrict__ ei) {
    int e = blockIdx.x * blockDim.x + threadIdx.x;
    if (e < NEDGES) atomicAdd(&g_deg[ei[NEDGES + e]], 1);
}

__global__ void k_scan() {
    __shared__ int sh[1024];
    const int n = NNODES;
    int tid = threadIdx.x;
    const int chunk = (n + 1023) / 1024;
    int start = tid * chunk;
    int s = 0;
    for (int i = 0; i < chunk; i++) {
        int idx = start + i;
        if (idx < n) s += g_deg[idx] + 1;
    }
    sh[tid] = s;
    __syncthreads();
    for (int o = 1; o < 1024; o <<= 1) {
        int v = (tid >= o) ? sh[tid - o] : 0;
        __syncthreads();
        sh[tid] += v;
        __syncthreads();
    }
    int run = tid ? sh[tid - 1] : 0;
    for (int i = 0; i < chunk; i++) {
        int idx = start + i;
        if (idx < n) {
            g_off[idx] = run;
            g_cur[idx] = run;
            run += g_deg[idx] + 1;
        }
    }
    if (tid == 1023) g_off[n] = sh[1023];
}

__global__ void k_fill(const int* __restrict__ ei) {
    int e = blockIdx.x * blockDim.x + threadIdx.x;
    if (e >= ETOT) return;
    int src, dst;
    if (e < NEDGES) { src = ei[e]; dst = ei[NEDGES + e]; }
    else            { src = dst = e - NEDGES; }
    int pos = atomicAdd(&g_cur[dst], 1);
    g_csr[pos] = src;
}

// ---------------- weight pre-round: Wc[256][K] = tf32([Wl;Wr]) ---------------
__global__ void k_roundW(const float* __restrict__ Wl,
                         const float* __restrict__ Wr,
                         float* __restrict__ Wc, int K) {
    int i = blockIdx.x * blockDim.x + threadIdx.x;
    if (i >= 256 * K) return;
    int r = i / K, k = i % K;
    float v = (r < 128) ? Wl[r * K + k] : Wr[(r - 128) * K + k];
    Wc[i] = rnd_tf32(v);
}

// ---------------- TF32 tensor-core GEMM, 5-stage cp.async pipeline -----------
// Out[M,256] = X[M,K] @ Wc^T, Wc pre-rounded. APR: A is pre-rounded too
// (skip cvt). 128x128 block tile, 8 warps, 64x32 warp tile.
#define ST    5
#define PAD   20
#define STGW  (128 * PAD)
#define GSMEM (ST * 2 * STGW * 4)

__device__ __forceinline__ void cp16(uint32_t sa, const void* g) {
    asm volatile("cp.async.cg.shared.global [%0], [%1], 16;" :: "r"(sa), "l"(g));
}

template <bool APR>
__global__ void __launch_bounds__(256, 2)
k_gemm_tf32(const float* __restrict__ X,
            const float* __restrict__ Wc,
            float* __restrict__ Out, int K) {
    extern __shared__ float sm[];
    float* Asm = sm;
    float* Bsm = sm + ST * STGW;
    uint32_t Abase = (uint32_t)__cvta_generic_to_shared(Asm);
    uint32_t Bbase = (uint32_t)__cvta_generic_to_shared(Bsm);

    int t = threadIdx.x;
    int m0 = blockIdx.x * 128, n0 = blockIdx.y * 128;
    int lane = t & 31;
    int wid = t >> 5;
    int wm = (wid >> 2) * 64;
    int wn = (wid & 3) * 32;
    int g = lane >> 2, c = lane & 3;

    int rowA0 = t >> 2, rowA1 = (t + 256) >> 2;
    int q0 = (t & 3) * 4;
    int ga0 = m0 + rowA0; if (ga0 >= NNODES) ga0 = 0;
    int ga1 = m0 + rowA1; if (ga1 >= NNODES) ga1 = 0;
    const float* ap0 = X + (size_t)ga0 * K + q0;
    const float* ap1 = X + (size_t)ga1 * K + q0;
    const float* bp0 = Wc + (size_t)(n0 + rowA0) * K + q0;
    const float* bp1 = Wc + (size_t)(n0 + rowA1) * K + q0;
    uint32_t sa0 = Abase + (uint32_t)(rowA0 * PAD + q0) * 4;
    uint32_t sa1 = Abase + (uint32_t)(rowA1 * PAD + q0) * 4;
    uint32_t sb0 = Bbase + (uint32_t)(rowA0 * PAD + q0) * 4;
    uint32_t sb1 = Bbase + (uint32_t)(rowA1 * PAD + q0) * 4;

    int nk = K >> 4;

#define ISSUE(slot, kt_)                                             \
    {   uint32_t so = (uint32_t)(slot) * (STGW * 4);                 \
        size_t go = (size_t)(kt_) * 16;                              \
        cp16(sa0 + so, ap0 + go); cp16(sa1 + so, ap1 + go);          \
        cp16(sb0 + so, bp0 + go); cp16(sb1 + so, bp1 + go); }

#pragma unroll
    for (int s = 0; s < ST - 1; s++) {
        if (s < nk) ISSUE(s, s);
        asm volatile("cp.async.commit_group;");
    }

    float acc[4][4][4];
#pragma unroll
    for (int i = 0; i < 4; i++)
#pragma unroll
        for (int j = 0; j < 4; j++)
#pragma unroll
            for (int q = 0; q < 4; q++) acc[i][j][q] = 0.f;

    for (int kt = 0; kt < nk; kt++) {
        asm volatile("cp.async.wait_group %0;" :: "n"(ST - 2));
        __syncthreads();

        int nxt = kt + ST - 1;
        if (nxt < nk) ISSUE(nxt % ST, nxt);
        asm volatile("cp.async.commit_group;");

        const float* As = Asm + (kt % ST) * STGW;
        const float* Bs = Bsm + (kt % ST) * STGW;
#pragma unroll
        for (int s = 0; s < 2; s++) {
            int ks = s * 8;
            unsigned bf[4][2];
#pragma unroll
            for (int j = 0; j < 4; j++) {
                const float* br = Bs + (wn + j * 8 + g) * PAD + ks + c;
                bf[j][0] = __float_as_uint(br[0]);      // W pre-rounded
                bf[j][1] = __float_as_uint(br[4]);
            }
#pragma unroll
            for (int i = 0; i < 4; i++) {
                const float* ar0 = As + (wm + i * 16 + g) * PAD + ks + c;
                const float* ar1 = As + (wm + i * 16 + g + 8) * PAD + ks + c;
                unsigned a0, a1, a2, a3;
                if (APR) {
                    a0 = __float_as_uint(ar0[0]);
                    a1 = __float_as_uint(ar1[0]);
                    a2 = __float_as_uint(ar0[4]);
                    a3 = __float_as_uint(ar1[4]);
                } else {
                    a0 = f2tf32(ar0[0]);
                    a1 = f2tf32(ar1[0]);
                    a2 = f2tf32(ar0[4]);
                    a3 = f2tf32(ar1[4]);
                }
#pragma unroll
                for (int j = 0; j < 4; j++) {
                    asm volatile(
                        "mma.sync.aligned.m16n8k8.row.col.f32.tf32.tf32.f32 "
                        "{%0,%1,%2,%3}, {%4,%5,%6,%7}, {%8,%9}, {%0,%1,%2,%3};"
                        : "+f"(acc[i][j][0]), "+f"(acc[i][j][1]),
                          "+f"(acc[i][j][2]), "+f"(acc[i][j][3])
                        : "r"(a0), "r"(a1), "r"(a2), "r"(a3),
                          "r"(bf[j][0]), "r"(bf[j][1]));
                }
            }
        }
    }
#undef ISSUE

#pragma unroll
    for (int i = 0; i < 4; i++) {
        int row0 = m0 + wm + i * 16 + g;
        int row1 = row0 + 8;
#pragma unroll
        for (int j = 0; j < 4; j++) {
            int col = n0 + wn + j * 8 + c * 2;
            if (row0 < NNODES)
                *(float2*)(Out + (size_t)row0 * 256 + col) =
                    make_float2(acc[i][j][0], acc[i][j][1]);
            if (row1 < NNODES)
                *(float2*)(Out + (size_t)row1 * 256 + col) =
                    make_float2(acc[i][j][2], acc[i][j][3]);
        }
    }
}

// ---------------- GATv2 attention: warp-per-dst, batch-4 (R6 body) -----------
// roundOut: round H to tf32 in epilogue (layer 0 only) so the next GEMM can
// skip its A-operand cvt. Identical rounding point to in-GEMM cvt.
__global__ void k_attn(const float* __restrict__ XLR,
                       const float* __restrict__ att,
                       const float* __restrict__ bias,
                       float* __restrict__ H, int roundOut) {
    int warp = (blockIdx.x * blockDim.x + threadIdx.x) >> 5;
    int lane = threadIdx.x & 31;
    if (warp >= NNODES) return;
    int dst = warp;
    int c4 = lane << 2;

    float4 xr = *(const float4*)(XLR + (size_t)dst * 256 + 128 + c4);
    float4 av = *(const float4*)(att + c4);

    int beg = g_off[dst], end = g_off[dst + 1];

    float s = 0.f;
    float cx = 0.f, cy = 0.f, cz = 0.f, cw = 0.f;

#define EDGE(v)                                                             \
    {   float t0 = (v).x + xr.x, t1 = (v).y + xr.y;                         \
        float t2 = (v).z + xr.z, t3 = (v).w + xr.w;                         \
        t0 = (t0 > 0.f) ? t0 : 0.2f * t0;                                   \
        t1 = (t1 > 0.f) ? t1 : 0.2f * t1;                                   \
        t2 = (t2 > 0.f) ? t2 : 0.2f * t2;                                   \
        t3 = (t3 > 0.f) ? t3 : 0.2f * t3;                                   \
        float p = av.x * t0 + av.y * t1 + av.z * t2 + av.w * t3;            \
        p += __shfl_xor_sync(0xffffffffu, p, 1);                            \
        p += __shfl_xor_sync(0xffffffffu, p, 2);                            \
        p += __shfl_xor_sync(0xffffffffu, p, 4);                            \
        float w = __expf(p);                                                \
        s += w; cx += w * (v).x; cy += w * (v).y;                           \
        cz += w * (v).z; cw += w * (v).w; }

    int jj = beg;
    for (; jj + 4 <= end; jj += 4) {
        int s0 = g_csr[jj], s1 = g_csr[jj + 1];
        int s2 = g_csr[jj + 2], s3 = g_csr[jj + 3];
        float4 v0 = *(const float4*)(XLR + (size_t)s0 * 256 + c4);
        float4 v1 = *(const float4*)(XLR + (size_t)s1 * 256 + c4);
        float4 v2 = *(const float4*)(XLR + (size_t)s2 * 256 + c4);
        float4 v3 = *(const float4*)(XLR + (size_t)s3 * 256 + c4);
        EDGE(v0); EDGE(v1); EDGE(v2); EDGE(v3);
    }
    for (; jj < end; jj++) {
        int sn = g_csr[jj];
        float4 v = *(const float4*)(XLR + (size_t)sn * 256 + c4);
        EDGE(v);
    }
#undef EDGE

    float inv = 1.f / s;
    float4 bv = *(const float4*)(bias + c4);
    float4 o = make_float4(cx * inv + bv.x, cy * inv + bv.y,
                           cz * inv + bv.z, cw * inv + bv.w);
    if (roundOut) {
        o.x = rnd_tf32(o.x); o.y = rnd_tf32(o.y);
        o.z = rnd_tf32(o.z); o.w = rnd_tf32(o.w);
    }
    *(float4*)(H + (size_t)dst * 128 + c4) = o;
}

// ---------------- down projection: Out[N,32] = H[N,128] @ W[32,128]^T + b ----
__global__ void k_down(const float* __restrict__ Hin,
                       const float* __restrict__ W,
                       const float* __restrict__ b,
                       float* __restrict__ Out) {
    __shared__ float Ws[128 * 33];
    __shared__ float Hs[8 * 128];
    int tid = threadIdx.x;
    for (int l = tid; l < 32 * 128; l += 256) {
        int c = l / 128, k = l % 128;
        Ws[k * 33 + c] = W[l];
    }
    int n0 = blockIdx.x * 8;
    for (int l = tid; l < 8 * 128; l += 256)
        Hs[l] = Hin[(size_t)n0 * 128 + l];
    __syncthreads();
    int nd = tid >> 5, c = tid & 31;
    float acc = 0.f;
#pragma unroll 16
    for (int k = 0; k < 128; k++)
        acc += Hs[nd * 128 + k] * Ws[k * 33 + c];
    Out[(size_t)(n0 + nd) * 32 + c] = acc + b[c];
}

// ---------------- launch -----------------------------------------------------
extern "C" void kernel_launch(void* const* d_in, const int* in_sizes, int n_in,
                              void* d_out, int out_size) {
    const float* x    = (const float*)d_in[0];
    const int*   ei   = (const int*)d_in[1];
    const float* Wl0  = (const float*)d_in[2];
    const float* Wr0  = (const float*)d_in[3];
    const float* att0 = (const float*)d_in[4];
    const float* b0   = (const float*)d_in[5];
    const float* Wl1  = (const float*)d_in[6];
    const float* Wr1  = (const float*)d_in[7];
    const float* att1 = (const float*)d_in[8];
    const float* b1   = (const float*)d_in[9];
    const float* dW   = (const float*)d_in[10];
    const float* db   = (const float*)d_in[11];
    float* out = (float*)d_out;

    float *xlr_p = nullptr, *h_p = nullptr, *w0_p = nullptr, *w1_p = nullptr;
    int  *deg_p = nullptr;
    cudaGetSymbolAddress((void**)&xlr_p, g_XLR);
    cudaGetSymbolAddress((void**)&h_p, g_H);
    cudaGetSymbolAddress((void**)&w0_p, g_W0);
    cudaGetSymbolAddress((void**)&w1_p, g_W1);
    cudaGetSymbolAddress((void**)&deg_p, g_deg);

    static cudaStream_t s2 = nullptr;
    static cudaEvent_t evFork = nullptr, evJoin = nullptr;
    if (!s2) {
        cudaFuncSetAttribute(k_gemm_tf32<false>,
                             cudaFuncAttributeMaxDynamicSharedMemorySize, GSMEM);
        cudaFuncSetAttribute(k_gemm_tf32<true>,
                             cudaFuncAttributeMaxDynamicSharedMemorySize, GSMEM);
        cudaStreamCreateWithFlags(&s2, cudaStreamNonBlocking);
        cudaEventCreateWithFlags(&evFork, cudaEventDisableTiming);
        cudaEventCreateWithFlags(&evJoin, cudaEventDisableTiming);
    }

    cudaStream_t s0 = 0;

    // ---- fork: CSR build on s2 || weight round + GEMM layer 0 on s0 ----
    cudaEventRecord(evFork, s0);
    cudaStreamWaitEvent(s2, evFork, 0);

    cudaMemsetAsync(deg_p, 0, NNODES * sizeof(int), s2);
    k_deg_count<<<(NEDGES + 255) / 256, 256, 0, s2>>>(ei);
    k_scan<<<1, 1024, 0, s2>>>();
    k_fill<<<(ETOT + 255) / 256, 256, 0, s2>>>(ei);
    cudaEventRecord(evJoin, s2);

    k_roundW<<<(256 * DIN + 255) / 256, 256, 0, s0>>>(Wl0, Wr0, w0_p, DIN);
    k_roundW<<<(256 * HID + 255) / 256, 256, 0, s0>>>(Wl1, Wr1, w1_p, HID);

    dim3 gg((NNODES + 127) / 128, 2);
    k_gemm_tf32<false><<<gg, 256, GSMEM, s0>>>(x, w0_p, xlr_p, DIN);

    cudaStreamWaitEvent(s0, evJoin, 0);

    // layer 0 attention (rounds H to tf32 for the next GEMM)
    k_attn<<<(NNODES * 32 + 255) / 256, 256, 0, s0>>>(xlr_p, att0, b0, h_p, 1);

    // layer 1 (A pre-rounded -> skip cvt)
    k_gemm_tf32<true><<<gg, 256, GSMEM, s0>>>(h_p, w1_p, xlr_p, HID);
    k_attn<<<(NNODES * 32 + 255) / 256, 256, 0, s0>>>(xlr_p, att1, b1, h_p, 0);

    // down proj
    k_down<<<NNODES / 8, 256, 0, s0>>>(h_p, dW, db, out);
}